// round 13
// baseline (speedup 1.0000x reference)
#include <cuda_runtime.h>
#include <cuda_bf16.h>
#include <math.h>
#include <stdint.h>

// Problem constants (fixed by the dataset)
#define T_TOK 8192
#define D_DIM 1024
#define E_EXP 8
#define H_DIM 4096

// ---------------- device-global scratch (256MB total — proven envelope) ----------------
__device__ int   g_cnt[E_EXP];
__device__ int   g_off[E_EXP];
__device__ int   g_tok[E_EXP * T_TOK];
__device__ float g_wt [E_EXP * T_TOK];
// shared transposed-weight buffer: W1t during gemm1, then W2t during gemm2.
__device__ __align__(256) __nv_bfloat16 g_wth[(size_t)E_EXP * H_DIM * D_DIM];  // 64MB
__device__ __align__(256) __nv_bfloat16 g_wtl[(size_t)E_EXP * H_DIM * D_DIM];  // 64MB
__device__ __align__(256) __nv_bfloat16 g_hh [(size_t)T_TOK * 2 * H_DIM];      // 64MB
__device__ __align__(256) __nv_bfloat16 g_hl [(size_t)T_TOK * 2 * H_DIM];      // 64MB

// ---------------- helpers ----------------
__device__ __forceinline__ uint32_t smem_u32(const void* p) {
    uint32_t a;
    asm("{ .reg .u64 t; cvta.to.shared.u64 t, %1; cvt.u32.u64 %0, t; }" : "=r"(a) : "l"(p));
    return a;
}
__device__ __forceinline__ void ldsm4(uint32_t* r, uint32_t addr) {
    asm volatile("ldmatrix.sync.aligned.m8n8.x4.shared.b16 {%0,%1,%2,%3}, [%4];"
                 : "=r"(r[0]), "=r"(r[1]), "=r"(r[2]), "=r"(r[3]) : "r"(addr));
}
__device__ __forceinline__ void mma_bf16(float* c, const uint32_t* a, const uint32_t* b) {
    asm volatile("mma.sync.aligned.m16n8k16.row.col.f32.bf16.bf16.f32 "
                 "{%0,%1,%2,%3}, {%4,%5,%6,%7}, {%8,%9}, {%0,%1,%2,%3};"
                 : "+f"(c[0]), "+f"(c[1]), "+f"(c[2]), "+f"(c[3])
                 : "r"(a[0]), "r"(a[1]), "r"(a[2]), "r"(a[3]), "r"(b[0]), "r"(b[1]));
}
__device__ __forceinline__ void cp16(uint32_t s, const void* g) {
    asm volatile("cp.async.cg.shared.global [%0], [%1], 16;" :: "r"(s), "l"(g) : "memory");
}
#define CP_COMMIT() asm volatile("cp.async.commit_group;" ::: "memory")
#define CP_WAIT0()  asm volatile("cp.async.wait_group 0;" ::: "memory")
#define CP_WAIT1()  asm volatile("cp.async.wait_group 1;" ::: "memory")

// pack {lo=bf16(a), hi=bf16(b)} in one cvt
__device__ __forceinline__ uint32_t cvt2(float a, float b) {
    uint32_t r;
    asm("cvt.rn.bf16x2.f32 %0, %1, %2;" : "=r"(r) : "f"(b), "f"(a));
    return r;
}
__device__ __forceinline__ float gelu_exact(float v) {
    return 0.5f * v * (1.0f + erff(v * 0.70710678118654752f));
}

// ---------------- small kernels (R1-proven) ----------------
__global__ void zero_kernel(float* __restrict__ out, int n) {
    int i = blockIdx.x * blockDim.x + threadIdx.x;
    if (i < E_EXP) g_cnt[i] = 0;
    for (int j = i; j < n; j += gridDim.x * blockDim.x) out[j] = 0.0f;
}

__global__ void router_kernel(const float* __restrict__ x, const float* __restrict__ Wg) {
    int warp = (blockIdx.x * blockDim.x + threadIdx.x) >> 5;
    int lane = threadIdx.x & 31;
    if (warp >= T_TOK) return;
    const float* xr = x + (size_t)warp * D_DIM;
    float acc[E_EXP];
#pragma unroll
    for (int e = 0; e < E_EXP; e++) acc[e] = 0.0f;
    for (int k = lane; k < D_DIM; k += 32) {
        float xv = xr[k];
        const float* wr = Wg + (size_t)k * E_EXP;
#pragma unroll
        for (int e = 0; e < E_EXP; e++) acc[e] = fmaf(xv, wr[e], acc[e]);
    }
#pragma unroll
    for (int e = 0; e < E_EXP; e++)
#pragma unroll
        for (int o = 16; o > 0; o >>= 1) acc[e] += __shfl_xor_sync(0xffffffffu, acc[e], o);
    if (lane == 0) {
        float mx = acc[0];
#pragma unroll
        for (int e = 1; e < E_EXP; e++) mx = fmaxf(mx, acc[e]);
        float p[E_EXP], s = 0.0f;
#pragma unroll
        for (int e = 0; e < E_EXP; e++) { p[e] = expf(acc[e] - mx); s += p[e]; }
        float inv = 1.0f / s;
        int i1 = 0; float v1 = p[0];
#pragma unroll
        for (int e = 1; e < E_EXP; e++) if (p[e] > v1) { v1 = p[e]; i1 = e; }
        int i2 = -1; float v2 = -1.0f;
#pragma unroll
        for (int e = 0; e < E_EXP; e++) if (e != i1 && p[e] > v2) { v2 = p[e]; i2 = e; }
        int p1 = atomicAdd(&g_cnt[i1], 1);
        g_tok[i1 * T_TOK + p1] = warp; g_wt[i1 * T_TOK + p1] = v1 * inv;
        int p2 = atomicAdd(&g_cnt[i2], 1);
        g_tok[i2 * T_TOK + p2] = warp; g_wt[i2 * T_TOK + p2] = v2 * inv;
    }
}

__global__ void scan_kernel() {
    if (threadIdx.x == 0) {
        int s = 0;
#pragma unroll
        for (int e = 0; e < E_EXP; e++) { g_off[e] = s; s += g_cnt[e]; }
    }
}

// transpose + split: src[e][R][C] fp32 -> g_wth/g_wtl [e][C][R] bf16 hi/lo.
// Writes vectorized as uint32 pairs (coalesced 4B stores).
// dst[col c0+c][row r0+2p (+1)] = bf16(src[row r0+2p (+1)][col c0+c]) = t[2p (+1)][c]
__global__ void split_w_kernel(const float* __restrict__ src, int R, int C) {
    __shared__ float t[32][33];
    int e = blockIdx.z;
    int c0 = blockIdx.x * 32, r0 = blockIdx.y * 32;
    int tx = threadIdx.x, ty = threadIdx.y;     // 32 x 8
    const float* s = src + (size_t)e * R * C;
#pragma unroll
    for (int i = 0; i < 4; i++)
        t[ty + i * 8][tx] = s[(size_t)(r0 + ty + i * 8) * C + c0 + tx];
    __syncthreads();
    size_t base = (size_t)e * R * C;
    int tfl = ty * 32 + tx;                     // 0..255
    int c = tfl >> 3;                           // 0..31 (column within tile)
#pragma unroll
    for (int it = 0; it < 2; it++) {
        int p = (tfl & 7) + it * 8;             // pair index 0..15 (row pair)
        float v0 = t[2 * p][c], v1 = t[2 * p + 1][c];   // FIXED: rows 2p,2p+1 of column c
        uint32_t h = cvt2(v0, v1);
        float ha = __uint_as_float(h << 16), hb = __uint_as_float(h & 0xFFFF0000u);
        uint32_t l = cvt2(v0 - ha, v1 - hb);
        size_t o = base + (size_t)(c0 + c) * R + r0 + 2 * p;
        *(uint32_t*)((uint16_t*)g_wth + o) = h;
        *(uint32_t*)((uint16_t*)g_wtl + o) = l;
    }
}

// ---------------- HMMA GEMM ----------------
// Sub-stage (16KB): 128 rows x 128B. Row r, 8 chunks of 16B at slot ((c ^ (r&7)) << 4):
//   c0,c1: A_hi k0-7,k8-15 | c2,c3: A_lo | c4,c5: B_hi | c6,c7: B_lo
// Stage (32KB) = 2 sub-stages. 3-stage ring = 96KB static smem, 2 CTAs/SM.
#define BM 128
#define BN 128
#define SUB_BYTES 16384
#define STAGE_BYTES 32768
#define N_BUF 3

__device__ __forceinline__ void load_A16(float* f, const float* a) {
    const float4* p = (const float4*)a;
#pragma unroll
    for (int q = 0; q < 4; q++) {
        float4 v = p[q];
        f[4 * q] = v.x; f[4 * q + 1] = v.y; f[4 * q + 2] = v.z; f[4 * q + 3] = v.w;
    }
}

// convert 16 fp32 -> hi/lo bf16, store into sub-stage row r at chunk base cbase
__device__ __forceinline__ void cvt_store_row(uint32_t sb, int r, int cbase, const float* f) {
    uint32_t rb = sb + (uint32_t)r * 128;
    uint32_t rx = (uint32_t)(r & 7);
#pragma unroll
    for (int half = 0; half < 2; half++) {
        uint32_t hi[4], lo[4];
#pragma unroll
        for (int q = 0; q < 4; q++) {
            float a = f[half * 8 + 2 * q], b = f[half * 8 + 2 * q + 1];
            uint32_t h = cvt2(a, b);
            float ha = __uint_as_float(h << 16);
            float hb = __uint_as_float(h & 0xFFFF0000u);
            hi[q] = h;
            lo[q] = cvt2(a - ha, b - hb);
        }
        uint32_t ah = rb + ((((uint32_t)(cbase + half)) ^ rx) << 4);
        uint32_t al = rb + ((((uint32_t)(cbase + 2 + half)) ^ rx) << 4);
        asm volatile("st.shared.v4.b32 [%0], {%1,%2,%3,%4};"
                     :: "r"(ah), "r"(hi[0]), "r"(hi[1]), "r"(hi[2]), "r"(hi[3]));
        asm volatile("st.shared.v4.b32 [%0], {%1,%2,%3,%4};"
                     :: "r"(al), "r"(lo[0]), "r"(lo[1]), "r"(lo[2]), "r"(lo[3]));
    }
}

// cp.async one operand row for one k16 sub-stage; cbase 0 = A slots, 4 = B slots.
__device__ __forceinline__ void cp4(uint32_t sb, int r, uint32_t cbase,
                                    const char* ph, const char* pl, size_t kb) {
    uint32_t rb = sb + (uint32_t)r * 128;
    uint32_t rx = (uint32_t)(r & 7);
    cp16(rb + (((cbase + 0u) ^ rx) << 4), ph + kb);
    cp16(rb + (((cbase + 1u) ^ rx) << 4), ph + kb + 16);
    cp16(rb + (((cbase + 2u) ^ rx) << 4), pl + kb);
    cp16(rb + (((cbase + 3u) ^ rx) << 4), pl + kb + 16);
}

// one k16 sub-stage; acc[16][4] = [mtile*8+ntile][frag]; warp tile 32x64.
__device__ __forceinline__ void compute_sub(uint32_t sb, float acc[16][4]) {
    int tid = threadIdx.x;
    int lane = tid & 31;
    int wid = tid >> 5;
    int wm = (wid & 3) * 32;
    int wn = (wid >> 2) * 64;
    int g = lane >> 3, lr = lane & 7;

    int aRow0 = wm + ((g & 1) << 3) + lr;
    uint32_t ah = (uint32_t)(g >> 1);
    int bRow0 = wn + ((g >> 1) << 3) + lr;
    uint32_t bh_ = (uint32_t)(g & 1);

    uint32_t Ah[2][4], Al[2][4];
#pragma unroll
    for (int t = 0; t < 2; t++) {
        uint32_t row = (uint32_t)(aRow0 + 16 * t);
        uint32_t rb = sb + row * 128, rx = row & 7;
        ldsm4(Ah[t], rb + (((0u + ah) ^ rx) << 4));
        ldsm4(Al[t], rb + (((2u + ah) ^ rx) << 4));
    }
#pragma unroll
    for (int q = 0; q < 4; q++) {
        uint32_t Bh[4], Bl[4];
        uint32_t row = (uint32_t)(bRow0 + 16 * q);
        uint32_t rb = sb + row * 128, rx = row & 7;
        ldsm4(Bh, rb + (((4u + bh_) ^ rx) << 4));
        ldsm4(Bl, rb + (((6u + bh_) ^ rx) << 4));
#pragma unroll
        for (int t = 0; t < 2; t++)
#pragma unroll
            for (int jj = 0; jj < 2; jj++) {
                float* c = acc[t * 8 + q * 2 + jj];
                mma_bf16(c, Ah[t], &Bh[jj * 2]);   // hi*hi
                mma_bf16(c, Ah[t], &Bl[jj * 2]);   // hi*lo
                mma_bf16(c, Al[t], &Bh[jj * 2]);   // lo*hi
            }
    }
}

// 3-stage interleaved 32-k mainloop. Each thread services ONE operand row:
//   inline mode: fp32 LDG + cvt + STS into chunk base 0
//   async mode: cp.async pre-split bf16 hi/lo into chunk base `cbase`
template <int KT2>
__device__ __forceinline__ void gemm_mainloop(uint32_t sbase, int r, bool inlineLoad,
                                              const float* fsrc,
                                              const char* ph, const char* pl, uint32_t cbase,
                                              float acc[16][4]) {
    // prologue: fill buffers 0 and 1
    if (inlineLoad) {
        float f[16];
        load_A16(f, fsrc);      cvt_store_row(sbase, r, 0, f);
        load_A16(f, fsrc + 16); cvt_store_row(sbase + SUB_BYTES, r, 0, f);
        load_A16(f, fsrc + 32); cvt_store_row(sbase + STAGE_BYTES, r, 0, f);
        load_A16(f, fsrc + 48); cvt_store_row(sbase + STAGE_BYTES + SUB_BYTES, r, 0, f);
    } else {
        cp4(sbase, r, cbase, ph, pl, 0);
        cp4(sbase + SUB_BYTES, r, cbase, ph, pl, 32);
        CP_COMMIT();
        cp4(sbase + STAGE_BYTES, r, cbase, ph, pl, 64);
        cp4(sbase + STAGE_BYTES + SUB_BYTES, r, cbase, ph, pl, 96);
        CP_COMMIT();
    }
    CP_WAIT1();          // buffer 0 ready
    __syncthreads();
    int buf = 0;
    for (int kt = 0; kt < KT2; kt++) {
        uint32_t cur = sbase + (uint32_t)buf * STAGE_BYTES;
        int nb = buf + 2; if (nb >= N_BUF) nb -= N_BUF;
        uint32_t nxt = sbase + (uint32_t)nb * STAGE_BYTES;
        bool more = (kt + 2 < KT2);
        float fn[16];
        int k0 = (kt + 2) * 32;
        if (more) {  // start loads for buffer kt+2; MMAs below hide the latency
            if (inlineLoad) load_A16(fn, fsrc + k0);
            else cp4(nxt, r, cbase, ph, pl, (size_t)k0 * 2);
        }
        compute_sub(cur, acc);
        if (more) {
            if (inlineLoad) {
                cvt_store_row(nxt, r, 0, fn);
                load_A16(fn, fsrc + k0 + 16);
            } else {
                cp4(nxt + SUB_BYTES, r, cbase, ph, pl, (size_t)(k0 + 16) * 2);
                CP_COMMIT();
            }
        }
        compute_sub(cur + SUB_BYTES, acc);
        if (more && inlineLoad) cvt_store_row(nxt + SUB_BYTES, r, 0, fn);
        // ensure buffer for kt+1 is ready
        if (more) CP_WAIT1(); else CP_WAIT0();
        __syncthreads();
        if (++buf == N_BUF) buf = 0;
    }
}

// GEMM1: h = gelu(x[tok] @ W1[e] + b1) -> g_hh/g_hl.  A inline fp32, B async W1t.
__global__ __launch_bounds__(256, 2)
void gemm1_kernel(const float* __restrict__ x, const float* __restrict__ b1) {
    __shared__ __align__(128) char smem[N_BUF * STAGE_BYTES];
    int e = blockIdx.z;
    int cnt = g_cnt[e];
    int row0 = blockIdx.y * BM;
    if (row0 >= cnt) return;
    int col0 = blockIdx.x * BN;
    int off = g_off[e];
    int tid = threadIdx.x;
    uint32_t sbase = smem_u32(smem);

    int r = tid & 127;
    bool isA = tid < 128;
    const float* fsrc = 0; const char* ph = 0; const char* pl = 0;
    if (isA) {
        int rA = min(row0 + r, cnt - 1);
        fsrc = x + (size_t)g_tok[e * T_TOK + rA] * D_DIM;
    } else {
        size_t o = ((size_t)e * H_DIM * D_DIM + (size_t)(col0 + r) * D_DIM) * 2;
        ph = (const char*)g_wth + o;
        pl = (const char*)g_wtl + o;
    }

    float acc[16][4];
#pragma unroll
    for (int i = 0; i < 16; i++)
#pragma unroll
        for (int j = 0; j < 4; j++) acc[i][j] = 0.0f;

    gemm_mainloop<D_DIM / 32>(sbase, r, isA, fsrc, ph, pl, 4u, acc);

    // epilogue: bias + gelu -> bf16 hi/lo scratch
    int lane = tid & 31, wid = tid >> 5;
    int wm = (wid & 3) * 32, wn = (wid >> 2) * 64;
    int mrow = row0 + wm + (lane >> 2);
    int ncol = col0 + wn + (lane & 3) * 2;
    const float* bg = b1 + (size_t)e * H_DIM;

#pragma unroll
    for (int t = 0; t < 2; t++)
#pragma unroll
        for (int j = 0; j < 8; j++) {
            float* c = acc[t * 8 + j];
            int cc = ncol + j * 8;
            float bias0 = bg[cc], bias1 = bg[cc + 1];
            int r1 = mrow + t * 16, r2 = r1 + 8;
            if (r1 < cnt) {
                float g0 = gelu_exact(c[0] + bias0), g1 = gelu_exact(c[1] + bias1);
                uint32_t h = cvt2(g0, g1);
                float ha = __uint_as_float(h << 16), hb = __uint_as_float(h & 0xFFFF0000u);
                size_t o = (size_t)(off + r1) * H_DIM + cc;
                *(uint32_t*)(g_hh + o) = h;
                *(uint32_t*)(g_hl + o) = cvt2(g0 - ha, g1 - hb);
            }
            if (r2 < cnt) {
                float g0 = gelu_exact(c[2] + bias0), g1 = gelu_exact(c[3] + bias1);
                uint32_t h = cvt2(g0, g1);
                float ha = __uint_as_float(h << 16), hb = __uint_as_float(h & 0xFFFF0000u);
                size_t o = (size_t)(off + r2) * H_DIM + cc;
                *(uint32_t*)(g_hh + o) = h;
                *(uint32_t*)(g_hl + o) = cvt2(g0 - ha, g1 - hb);
            }
        }
}

// GEMM2: out[tok] += w * (h @ W2[e] + b2).  A async h-split, B async W2t.
__global__ __launch_bounds__(256, 2)
void gemm2_kernel(const float* __restrict__ b2, float* __restrict__ out) {
    __shared__ __align__(128) char smem[N_BUF * STAGE_BYTES];
    int e = blockIdx.z;
    int cnt = g_cnt[e];
    int row0 = blockIdx.y * BM;
    if (row0 >= cnt) return;
    int col0 = blockIdx.x * BN;
    int off = g_off[e];
    int tid = threadIdx.x;
    uint32_t sbase = smem_u32(smem);

    int r = tid & 127;
    bool isA = tid < 128;
    const char* ph = 0; const char* pl = 0;
    uint32_t cbase;
    if (isA) {
        int rA = off + min(row0 + r, cnt - 1);
        size_t o = (size_t)rA * H_DIM * 2;
        ph = (const char*)g_hh + o;
        pl = (const char*)g_hl + o;
        cbase = 0u;
    } else {
        size_t o = ((size_t)e * H_DIM * D_DIM + (size_t)(col0 + r) * H_DIM) * 2;
        ph = (const char*)g_wth + o;
        pl = (const char*)g_wtl + o;
        cbase = 4u;
    }

    float acc[16][4];
#pragma unroll
    for (int i = 0; i < 16; i++)
#pragma unroll
        for (int j = 0; j < 4; j++) acc[i][j] = 0.0f;

    gemm_mainloop<H_DIM / 32>(sbase, r, false, 0, ph, pl, cbase, acc);

    int lane = tid & 31, wid = tid >> 5;
    int wm = (wid & 3) * 32, wn = (wid >> 2) * 64;
    int mrow = row0 + wm + (lane >> 2);
    int ncol = col0 + wn + (lane & 3) * 2;
    const float* bg = b2 + (size_t)e * D_DIM;

#pragma unroll
    for (int t = 0; t < 2; t++) {
        int r1 = mrow + t * 16, r2 = r1 + 8;
        int tok1 = 0, tok2 = 0; float w1 = 0.0f, w2 = 0.0f;
        if (r1 < cnt) { tok1 = g_tok[e * T_TOK + r1]; w1 = g_wt[e * T_TOK + r1]; }
        if (r2 < cnt) { tok2 = g_tok[e * T_TOK + r2]; w2 = g_wt[e * T_TOK + r2]; }
#pragma unroll
        for (int j = 0; j < 8; j++) {
            float* c = acc[t * 8 + j];
            int cc = ncol + j * 8;
            float bias0 = bg[cc], bias1 = bg[cc + 1];
            if (r1 < cnt) {
                float* o = out + (size_t)tok1 * D_DIM + cc;
                atomicAdd(o,     w1 * (c[0] + bias0));
                atomicAdd(o + 1, w1 * (c[1] + bias1));
            }
            if (r2 < cnt) {
                float* o = out + (size_t)tok2 * D_DIM + cc;
                atomicAdd(o,     w2 * (c[2] + bias0));
                atomicAdd(o + 1, w2 * (c[3] + bias1));
            }
        }
    }
}

// ---------------- launch ----------------
extern "C" void kernel_launch(void* const* d_in, const int* in_sizes, int n_in,
                              void* d_out, int out_size) {
    const float* x  = (const float*)d_in[0];
    const float* Wg = (const float*)d_in[1];
    const float* W1 = (const float*)d_in[2];
    const float* b1 = (const float*)d_in[3];
    const float* W2 = (const float*)d_in[4];
    const float* b2 = (const float*)d_in[5];
    float* out = (float*)d_out;

    zero_kernel<<<4096, 256>>>(out, out_size);
    router_kernel<<<T_TOK / 8, 256>>>(x, Wg);
    scan_kernel<<<1, 32>>>();

    // W1 [E][D][H] -> W1t [E][H][D] (hi/lo) in the shared weight buffer
    split_w_kernel<<<dim3(H_DIM / 32, D_DIM / 32, E_EXP), dim3(32, 8)>>>(W1, D_DIM, H_DIM);
    gemm1_kernel<<<dim3(H_DIM / BN, T_TOK / BM, E_EXP), 256>>>(x, b1);

    // W2 [E][H][D] -> W2t [E][D][H] (hi/lo), reusing the same buffer (stream-ordered)
    split_w_kernel<<<dim3(D_DIM / 32, H_DIM / 32, E_EXP), dim3(32, 8)>>>(W2, H_DIM, D_DIM);
    gemm2_kernel<<<dim3(D_DIM / BN, T_TOK / BM, E_EXP), 256>>>(b2, out);
}

// round 14
// speedup vs baseline: 1.3350x; 1.3350x over previous
#include <cuda_runtime.h>
#include <cuda_fp16.h>
#include <math.h>
#include <stdint.h>

// Problem constants (fixed by the dataset)
#define T_TOK 8192
#define D_DIM 1024
#define E_EXP 8
#define H_DIM 4096

// ---------------- device-global scratch (224MB total, < proven 256MB) ----------------
__device__ int   g_cnt[E_EXP];
__device__ int   g_off[E_EXP];
__device__ int   g_tok[E_EXP * T_TOK];
__device__ float g_wt [E_EXP * T_TOK];
__device__ __align__(256) __half g_xh [(size_t)T_TOK * D_DIM];             // 16MB
__device__ __align__(256) __half g_xl [(size_t)T_TOK * D_DIM];             // 16MB
// shared transposed-weight buffer (single fp16): W1t during gemm1, W2t during gemm2
__device__ __align__(256) __half g_wtr[(size_t)E_EXP * H_DIM * D_DIM];     // 64MB
__device__ __align__(256) __half g_hh [(size_t)T_TOK * 2 * H_DIM];         // 64MB
__device__ __align__(256) __half g_hl [(size_t)T_TOK * 2 * H_DIM];         // 64MB

// ---------------- helpers ----------------
__device__ __forceinline__ uint32_t smem_u32(const void* p) {
    uint32_t a;
    asm("{ .reg .u64 t; cvta.to.shared.u64 t, %1; cvt.u32.u64 %0, t; }" : "=r"(a) : "l"(p));
    return a;
}
__device__ __forceinline__ void ldsm4(uint32_t* r, uint32_t addr) {
    asm volatile("ldmatrix.sync.aligned.m8n8.x4.shared.b16 {%0,%1,%2,%3}, [%4];"
                 : "=r"(r[0]), "=r"(r[1]), "=r"(r[2]), "=r"(r[3]) : "r"(addr));
}
__device__ __forceinline__ void mma_fp16(float* c, const uint32_t* a, const uint32_t* b) {
    asm volatile("mma.sync.aligned.m16n8k16.row.col.f32.f16.f16.f32 "
                 "{%0,%1,%2,%3}, {%4,%5,%6,%7}, {%8,%9}, {%0,%1,%2,%3};"
                 : "+f"(c[0]), "+f"(c[1]), "+f"(c[2]), "+f"(c[3])
                 : "r"(a[0]), "r"(a[1]), "r"(a[2]), "r"(a[3]), "r"(b[0]), "r"(b[1]));
}
__device__ __forceinline__ void cp16(uint32_t s, const void* g) {
    asm volatile("cp.async.cg.shared.global [%0], [%1], 16;" :: "r"(s), "l"(g) : "memory");
}
#define CP_COMMIT() asm volatile("cp.async.commit_group;" ::: "memory")
#define CP_WAIT0()  asm volatile("cp.async.wait_group 0;" ::: "memory")

// pack two floats into fp16x2
__device__ __forceinline__ uint32_t cvth2(float a, float b) {
    __half2 t = __floats2half2_rn(a, b);
    return *(uint32_t*)&t;
}
__device__ __forceinline__ float2 h2f2(uint32_t h) {
    __half2 t = *(__half2*)&h;
    return __half22float2(t);
}
__device__ __forceinline__ float gelu_exact(float v) {
    return 0.5f * v * (1.0f + erff(v * 0.70710678118654752f));
}

// ---------------- small kernels (R1-proven) ----------------
__global__ void zero_kernel(float* __restrict__ out, int n) {
    int i = blockIdx.x * blockDim.x + threadIdx.x;
    if (i < E_EXP) g_cnt[i] = 0;
    for (int j = i; j < n; j += gridDim.x * blockDim.x) out[j] = 0.0f;
}

__global__ void router_kernel(const float* __restrict__ x, const float* __restrict__ Wg) {
    int warp = (blockIdx.x * blockDim.x + threadIdx.x) >> 5;
    int lane = threadIdx.x & 31;
    if (warp >= T_TOK) return;
    const float* xr = x + (size_t)warp * D_DIM;
    float acc[E_EXP];
#pragma unroll
    for (int e = 0; e < E_EXP; e++) acc[e] = 0.0f;
    for (int k = lane; k < D_DIM; k += 32) {
        float xv = xr[k];
        const float* wr = Wg + (size_t)k * E_EXP;
#pragma unroll
        for (int e = 0; e < E_EXP; e++) acc[e] = fmaf(xv, wr[e], acc[e]);
    }
#pragma unroll
    for (int e = 0; e < E_EXP; e++)
#pragma unroll
        for (int o = 16; o > 0; o >>= 1) acc[e] += __shfl_xor_sync(0xffffffffu, acc[e], o);
    if (lane == 0) {
        float mx = acc[0];
#pragma unroll
        for (int e = 1; e < E_EXP; e++) mx = fmaxf(mx, acc[e]);
        float p[E_EXP], s = 0.0f;
#pragma unroll
        for (int e = 0; e < E_EXP; e++) { p[e] = expf(acc[e] - mx); s += p[e]; }
        float inv = 1.0f / s;
        int i1 = 0; float v1 = p[0];
#pragma unroll
        for (int e = 1; e < E_EXP; e++) if (p[e] > v1) { v1 = p[e]; i1 = e; }
        int i2 = -1; float v2 = -1.0f;
#pragma unroll
        for (int e = 0; e < E_EXP; e++) if (e != i1 && p[e] > v2) { v2 = p[e]; i2 = e; }
        int p1 = atomicAdd(&g_cnt[i1], 1);
        g_tok[i1 * T_TOK + p1] = warp; g_wt[i1 * T_TOK + p1] = v1 * inv;
        int p2 = atomicAdd(&g_cnt[i2], 1);
        g_tok[i2 * T_TOK + p2] = warp; g_wt[i2 * T_TOK + p2] = v2 * inv;
    }
}

__global__ void scan_kernel() {
    if (threadIdx.x == 0) {
        int s = 0;
#pragma unroll
        for (int e = 0; e < E_EXP; e++) { g_off[e] = s; s += g_cnt[e]; }
    }
}

// split x: fp32 -> fp16 hi/lo
__global__ void split_x_kernel(const float* __restrict__ x) {
    int i = blockIdx.x * blockDim.x + threadIdx.x;
    int n4 = (T_TOK * D_DIM) / 4;
    if (i >= n4) return;
    float4 v = ((const float4*)x)[i];
    uint32_t h0 = cvth2(v.x, v.y), h1 = cvth2(v.z, v.w);
    float2 f0 = h2f2(h0), f1 = h2f2(h1);
    uint2 hp = make_uint2(h0, h1);
    uint2 lp = make_uint2(cvth2(v.x - f0.x, v.y - f0.y), cvth2(v.z - f1.x, v.w - f1.y));
    ((uint2*)g_xh)[i] = hp;
    ((uint2*)g_xl)[i] = lp;
}

// transpose + round: src[e][R][C] fp32 -> g_wtr [e][C][R] single fp16.
// dst[col c0+c][row r0+2p (+1)] = fp16(t[2p (+1)][c])   (R13-verified index order)
__global__ void split_w_kernel(const float* __restrict__ src, int R, int C) {
    __shared__ float t[32][33];
    int e = blockIdx.z;
    int c0 = blockIdx.x * 32, r0 = blockIdx.y * 32;
    int tx = threadIdx.x, ty = threadIdx.y;     // 32 x 8
    const float* s = src + (size_t)e * R * C;
#pragma unroll
    for (int i = 0; i < 4; i++)
        t[ty + i * 8][tx] = s[(size_t)(r0 + ty + i * 8) * C + c0 + tx];
    __syncthreads();
    size_t base = (size_t)e * R * C;
    int tfl = ty * 32 + tx;                     // 0..255
    int c = tfl >> 3;                           // 0..31
#pragma unroll
    for (int it = 0; it < 2; it++) {
        int p = (tfl & 7) + it * 8;             // row-pair index 0..15
        float v0 = t[2 * p][c], v1 = t[2 * p + 1][c];
        size_t o = base + (size_t)(c0 + c) * R + r0 + 2 * p;
        *(uint32_t*)((uint16_t*)g_wtr + o) = cvth2(v0, v1);
    }
}

// ---------------- HMMA GEMM (fp16, A split hi/lo, B single) ----------------
// Sub-stage (16KB): 128 rows x 128B. Row r, chunk c at slot ((c ^ (r&7)) << 4):
//   c0,c1: A_hi k0-7,k8-15 | c2,c3: A_lo | c4,c5: B k0-7,k8-15 | c6,c7 unused
#define BM 128
#define BN 128
#define SUB_BYTES 16384
#define STAGE_BYTES 32768

// cp.async A row (hi+lo, 4 chunks); kb = byte offset = k0*2
__device__ __forceinline__ void cpA(uint32_t sb, int r, const char* ah, const char* al, size_t kb) {
    uint32_t rb = sb + (uint32_t)r * 128;
    uint32_t rx = (uint32_t)(r & 7);
    cp16(rb + ((0u ^ rx) << 4), ah + kb);
    cp16(rb + ((1u ^ rx) << 4), ah + kb + 16);
    cp16(rb + ((2u ^ rx) << 4), al + kb);
    cp16(rb + ((3u ^ rx) << 4), al + kb + 16);
}
// cp.async B row (single, 2 chunks)
__device__ __forceinline__ void cpB(uint32_t sb, int r, const char* bp, size_t kb) {
    uint32_t rb = sb + (uint32_t)r * 128;
    uint32_t rx = (uint32_t)(r & 7);
    cp16(rb + ((4u ^ rx) << 4), bp + kb);
    cp16(rb + ((5u ^ rx) << 4), bp + kb + 16);
}

// one k16 sub-stage; acc[16][4] = [mtile*8+ntile][frag]; warp tile 32x64; 2 products.
__device__ __forceinline__ void compute_sub(uint32_t sb, float acc[16][4]) {
    int tid = threadIdx.x;
    int lane = tid & 31;
    int wid = tid >> 5;
    int wm = (wid & 3) * 32;
    int wn = (wid >> 2) * 64;
    int g = lane >> 3, lr = lane & 7;

    int aRow0 = wm + ((g & 1) << 3) + lr;
    uint32_t ah = (uint32_t)(g >> 1);
    int bRow0 = wn + ((g >> 1) << 3) + lr;
    uint32_t bh_ = (uint32_t)(g & 1);

    uint32_t Ah[2][4], Al[2][4];
#pragma unroll
    for (int t = 0; t < 2; t++) {
        uint32_t row = (uint32_t)(aRow0 + 16 * t);
        uint32_t rb = sb + row * 128, rx = row & 7;
        ldsm4(Ah[t], rb + (((0u + ah) ^ rx) << 4));
        ldsm4(Al[t], rb + (((2u + ah) ^ rx) << 4));
    }
#pragma unroll
    for (int q = 0; q < 4; q++) {
        uint32_t Bh[4];
        uint32_t row = (uint32_t)(bRow0 + 16 * q);
        uint32_t rb = sb + row * 128, rx = row & 7;
        ldsm4(Bh, rb + (((4u + bh_) ^ rx) << 4));
#pragma unroll
        for (int t = 0; t < 2; t++)
#pragma unroll
            for (int jj = 0; jj < 2; jj++) {
                float* c = acc[t * 8 + q * 2 + jj];
                mma_fp16(c, Ah[t], &Bh[jj * 2]);   // hi * B
                mma_fp16(c, Al[t], &Bh[jj * 2]);   // lo * B
            }
    }
}

// 2-stage mainloop (R10-proven shape), both operands async.
// Threads <128 service A row r (cpA), threads >=128 service B row r (cpB).
template <int KT2>
__device__ __forceinline__ void gemm_mainloop(uint32_t sbase, int r, bool isA,
                                              const char* ah, const char* al, const char* bp,
                                              float acc[16][4]) {
    if (isA) { cpA(sbase, r, ah, al, 0); cpA(sbase + SUB_BYTES, r, ah, al, 32); }
    else     { cpB(sbase, r, bp, 0);     cpB(sbase + SUB_BYTES, r, bp, 32); }
    CP_COMMIT();
    CP_WAIT0();
    __syncthreads();
    for (int kt = 0; kt < KT2; kt++) {
        uint32_t cur = sbase + (uint32_t)(kt & 1) * STAGE_BYTES;
        uint32_t nxt = sbase + (uint32_t)((kt + 1) & 1) * STAGE_BYTES;
        bool more = (kt + 1 < KT2);
        size_t kb = (size_t)(kt + 1) * 64;       // (kt+1)*32 elems * 2B
        if (more) {  // issue next-stage loads; MMAs below hide the latency
            if (isA) cpA(nxt, r, ah, al, kb);
            else     cpB(nxt, r, bp, kb);
        }
        compute_sub(cur, acc);
        if (more) {
            if (isA) cpA(nxt + SUB_BYTES, r, ah, al, kb + 32);
            else     cpB(nxt + SUB_BYTES, r, bp, kb + 32);
            CP_COMMIT();
        }
        compute_sub(cur + SUB_BYTES, acc);
        CP_WAIT0();
        __syncthreads();
    }
}

// GEMM1: h = gelu(x[tok] @ W1[e] + b1) -> g_hh/g_hl (fp16 hi/lo)
__global__ __launch_bounds__(256, 2)
void gemm1_kernel(const float* __restrict__ b1) {
    __shared__ __align__(128) char smem[2 * STAGE_BYTES];
    int e = blockIdx.z;
    int cnt = g_cnt[e];
    int row0 = blockIdx.y * BM;
    if (row0 >= cnt) return;
    int col0 = blockIdx.x * BN;
    int off = g_off[e];
    int tid = threadIdx.x;
    uint32_t sbase = smem_u32(smem);

    int r = tid & 127;
    bool isA = tid < 128;
    const char* ah = 0; const char* al = 0; const char* bp = 0;
    if (isA) {
        int rA = min(row0 + r, cnt - 1);
        size_t rowOff = (size_t)g_tok[e * T_TOK + rA] * D_DIM * 2;
        ah = (const char*)g_xh + rowOff;
        al = (const char*)g_xl + rowOff;
    } else {
        bp = (const char*)g_wtr + ((size_t)e * H_DIM * D_DIM + (size_t)(col0 + r) * D_DIM) * 2;
    }

    float acc[16][4];
#pragma unroll
    for (int i = 0; i < 16; i++)
#pragma unroll
        for (int j = 0; j < 4; j++) acc[i][j] = 0.0f;

    gemm_mainloop<D_DIM / 32>(sbase, r, isA, ah, al, bp, acc);

    // epilogue: bias + gelu -> fp16 hi/lo scratch
    int lane = tid & 31, wid = tid >> 5;
    int wm = (wid & 3) * 32, wn = (wid >> 2) * 64;
    int mrow = row0 + wm + (lane >> 2);
    int ncol = col0 + wn + (lane & 3) * 2;
    const float* bg = b1 + (size_t)e * H_DIM;

#pragma unroll
    for (int t = 0; t < 2; t++)
#pragma unroll
        for (int j = 0; j < 8; j++) {
            float* c = acc[t * 8 + j];
            int cc = ncol + j * 8;
            float bias0 = bg[cc], bias1 = bg[cc + 1];
            int r1 = mrow + t * 16, r2 = r1 + 8;
            if (r1 < cnt) {
                float g0 = gelu_exact(c[0] + bias0), g1 = gelu_exact(c[1] + bias1);
                uint32_t h = cvth2(g0, g1);
                float2 f = h2f2(h);
                size_t o = (size_t)(off + r1) * H_DIM + cc;
                *(uint32_t*)(g_hh + o) = h;
                *(uint32_t*)(g_hl + o) = cvth2(g0 - f.x, g1 - f.y);
            }
            if (r2 < cnt) {
                float g0 = gelu_exact(c[2] + bias0), g1 = gelu_exact(c[3] + bias1);
                uint32_t h = cvth2(g0, g1);
                float2 f = h2f2(h);
                size_t o = (size_t)(off + r2) * H_DIM + cc;
                *(uint32_t*)(g_hh + o) = h;
                *(uint32_t*)(g_hl + o) = cvth2(g0 - f.x, g1 - f.y);
            }
        }
}

// GEMM2: out[tok] += w * (h @ W2[e] + b2)
__global__ __launch_bounds__(256, 2)
void gemm2_kernel(const float* __restrict__ b2, float* __restrict__ out) {
    __shared__ __align__(128) char smem[2 * STAGE_BYTES];
    int e = blockIdx.z;
    int cnt = g_cnt[e];
    int row0 = blockIdx.y * BM;
    if (row0 >= cnt) return;
    int col0 = blockIdx.x * BN;
    int off = g_off[e];
    int tid = threadIdx.x;
    uint32_t sbase = smem_u32(smem);

    int r = tid & 127;
    bool isA = tid < 128;
    const char* ah = 0; const char* al = 0; const char* bp = 0;
    if (isA) {
        int rA = off + min(row0 + r, cnt - 1);
        size_t rowOff = (size_t)rA * H_DIM * 2;
        ah = (const char*)g_hh + rowOff;
        al = (const char*)g_hl + rowOff;
    } else {
        bp = (const char*)g_wtr + ((size_t)e * H_DIM * D_DIM + (size_t)(col0 + r) * H_DIM) * 2;
    }

    float acc[16][4];
#pragma unroll
    for (int i = 0; i < 16; i++)
#pragma unroll
        for (int j = 0; j < 4; j++) acc[i][j] = 0.0f;

    gemm_mainloop<H_DIM / 32>(sbase, r, isA, ah, al, bp, acc);

    int lane = tid & 31, wid = tid >> 5;
    int wm = (wid & 3) * 32, wn = (wid >> 2) * 64;
    int mrow = row0 + wm + (lane >> 2);
    int ncol = col0 + wn + (lane & 3) * 2;
    const float* bg = b2 + (size_t)e * D_DIM;

#pragma unroll
    for (int t = 0; t < 2; t++) {
        int r1 = mrow + t * 16, r2 = r1 + 8;
        int tok1 = 0, tok2 = 0; float w1 = 0.0f, w2 = 0.0f;
        if (r1 < cnt) { tok1 = g_tok[e * T_TOK + r1]; w1 = g_wt[e * T_TOK + r1]; }
        if (r2 < cnt) { tok2 = g_tok[e * T_TOK + r2]; w2 = g_wt[e * T_TOK + r2]; }
#pragma unroll
        for (int j = 0; j < 8; j++) {
            float* c = acc[t * 8 + j];
            int cc = ncol + j * 8;
            float bias0 = bg[cc], bias1 = bg[cc + 1];
            if (r1 < cnt) {
                float* o = out + (size_t)tok1 * D_DIM + cc;
                atomicAdd(o,     w1 * (c[0] + bias0));
                atomicAdd(o + 1, w1 * (c[1] + bias1));
            }
            if (r2 < cnt) {
                float* o = out + (size_t)tok2 * D_DIM + cc;
                atomicAdd(o,     w2 * (c[2] + bias0));
                atomicAdd(o + 1, w2 * (c[3] + bias1));
            }
        }
    }
}

// ---------------- launch ----------------
extern "C" void kernel_launch(void* const* d_in, const int* in_sizes, int n_in,
                              void* d_out, int out_size) {
    const float* x  = (const float*)d_in[0];
    const float* Wg = (const float*)d_in[1];
    const float* W1 = (const float*)d_in[2];
    const float* b1 = (const float*)d_in[3];
    const float* W2 = (const float*)d_in[4];
    const float* b2 = (const float*)d_in[5];
    float* out = (float*)d_out;

    zero_kernel<<<4096, 256>>>(out, out_size);
    router_kernel<<<T_TOK / 8, 256>>>(x, Wg);
    scan_kernel<<<1, 32>>>();
    split_x_kernel<<<(T_TOK * D_DIM / 4 + 255) / 256, 256>>>(x);

    // W1 [E][D][H] -> W1t [E][H][D] single fp16 (shared buffer)
    split_w_kernel<<<dim3(H_DIM / 32, D_DIM / 32, E_EXP), dim3(32, 8)>>>(W1, D_DIM, H_DIM);
    gemm1_kernel<<<dim3(H_DIM / BN, T_TOK / BM, E_EXP), 256>>>(b1);

    // W2 [E][H][D] -> W2t [E][D][H] single fp16 (same buffer, stream-ordered)
    split_w_kernel<<<dim3(D_DIM / 32, H_DIM / 32, E_EXP), dim3(32, 8)>>>(W2, H_DIM, D_DIM);
    gemm2_kernel<<<dim3(D_DIM / BN, T_TOK / BM, E_EXP), 256>>>(b2, out);
}

// round 15
// speedup vs baseline: 1.8944x; 1.4190x over previous
#include <cuda_runtime.h>
#include <cuda_fp16.h>
#include <math.h>
#include <stdint.h>

// Problem constants (fixed by the dataset)
#define T_TOK 8192
#define D_DIM 1024
#define E_EXP 8
#define H_DIM 4096

// ---------------- device-global scratch ----------------
__device__ int   g_cnt[E_EXP];
__device__ int   g_off[E_EXP];
__device__ int   g_tok[E_EXP * T_TOK];
__device__ float g_wt [E_EXP * T_TOK];
__device__ __align__(256) __half g_xh [(size_t)T_TOK * D_DIM];             // x fp16
// shared transposed-weight buffer (single fp16): W1t during gemm1, W2t during gemm2
__device__ __align__(256) __half g_wtr[(size_t)E_EXP * H_DIM * D_DIM];
__device__ __align__(256) __half g_hh [(size_t)T_TOK * 2 * H_DIM];         // h fp16

// ---------------- helpers ----------------
__device__ __forceinline__ uint32_t smem_u32(const void* p) {
    uint32_t a;
    asm("{ .reg .u64 t; cvta.to.shared.u64 t, %1; cvt.u32.u64 %0, t; }" : "=r"(a) : "l"(p));
    return a;
}
__device__ __forceinline__ void ldsm4(uint32_t* r, uint32_t addr) {
    asm volatile("ldmatrix.sync.aligned.m8n8.x4.shared.b16 {%0,%1,%2,%3}, [%4];"
                 : "=r"(r[0]), "=r"(r[1]), "=r"(r[2]), "=r"(r[3]) : "r"(addr));
}
__device__ __forceinline__ void mma_fp16(float* c, const uint32_t* a, const uint32_t* b) {
    asm volatile("mma.sync.aligned.m16n8k16.row.col.f32.f16.f16.f32 "
                 "{%0,%1,%2,%3}, {%4,%5,%6,%7}, {%8,%9}, {%0,%1,%2,%3};"
                 : "+f"(c[0]), "+f"(c[1]), "+f"(c[2]), "+f"(c[3])
                 : "r"(a[0]), "r"(a[1]), "r"(a[2]), "r"(a[3]), "r"(b[0]), "r"(b[1]));
}
__device__ __forceinline__ void cp16(uint32_t s, const void* g) {
    asm volatile("cp.async.cg.shared.global [%0], [%1], 16;" :: "r"(s), "l"(g) : "memory");
}
#define CP_COMMIT() asm volatile("cp.async.commit_group;" ::: "memory")
#define CP_WAIT0()  asm volatile("cp.async.wait_group 0;" ::: "memory")

__device__ __forceinline__ uint32_t cvth2(float a, float b) {
    __half2 t = __floats2half2_rn(a, b);
    return *(uint32_t*)&t;
}
__device__ __forceinline__ float gelu_exact(float v) {
    return 0.5f * v * (1.0f + erff(v * 0.70710678118654752f));
}

// ---------------- small kernels (R1-proven) ----------------
__global__ void zero_kernel(float* __restrict__ out, int n) {
    int i = blockIdx.x * blockDim.x + threadIdx.x;
    if (i < E_EXP) g_cnt[i] = 0;
    for (int j = i; j < n; j += gridDim.x * blockDim.x) out[j] = 0.0f;
}

__global__ void router_kernel(const float* __restrict__ x, const float* __restrict__ Wg) {
    int warp = (blockIdx.x * blockDim.x + threadIdx.x) >> 5;
    int lane = threadIdx.x & 31;
    if (warp >= T_TOK) return;
    const float* xr = x + (size_t)warp * D_DIM;
    float acc[E_EXP];
#pragma unroll
    for (int e = 0; e < E_EXP; e++) acc[e] = 0.0f;
    for (int k = lane; k < D_DIM; k += 32) {
        float xv = xr[k];
        const float* wr = Wg + (size_t)k * E_EXP;
#pragma unroll
        for (int e = 0; e < E_EXP; e++) acc[e] = fmaf(xv, wr[e], acc[e]);
    }
#pragma unroll
    for (int e = 0; e < E_EXP; e++)
#pragma unroll
        for (int o = 16; o > 0; o >>= 1) acc[e] += __shfl_xor_sync(0xffffffffu, acc[e], o);
    if (lane == 0) {
        float mx = acc[0];
#pragma unroll
        for (int e = 1; e < E_EXP; e++) mx = fmaxf(mx, acc[e]);
        float p[E_EXP], s = 0.0f;
#pragma unroll
        for (int e = 0; e < E_EXP; e++) { p[e] = expf(acc[e] - mx); s += p[e]; }
        float inv = 1.0f / s;
        int i1 = 0; float v1 = p[0];
#pragma unroll
        for (int e = 1; e < E_EXP; e++) if (p[e] > v1) { v1 = p[e]; i1 = e; }
        int i2 = -1; float v2 = -1.0f;
#pragma unroll
        for (int e = 0; e < E_EXP; e++) if (e != i1 && p[e] > v2) { v2 = p[e]; i2 = e; }
        int p1 = atomicAdd(&g_cnt[i1], 1);
        g_tok[i1 * T_TOK + p1] = warp; g_wt[i1 * T_TOK + p1] = v1 * inv;
        int p2 = atomicAdd(&g_cnt[i2], 1);
        g_tok[i2 * T_TOK + p2] = warp; g_wt[i2 * T_TOK + p2] = v2 * inv;
    }
}

__global__ void scan_kernel() {
    if (threadIdx.x == 0) {
        int s = 0;
#pragma unroll
        for (int e = 0; e < E_EXP; e++) { g_off[e] = s; s += g_cnt[e]; }
    }
}

// x: fp32 -> single fp16
__global__ void split_x_kernel(const float* __restrict__ x) {
    int i = blockIdx.x * blockDim.x + threadIdx.x;
    int n4 = (T_TOK * D_DIM) / 4;
    if (i >= n4) return;
    float4 v = ((const float4*)x)[i];
    ((uint2*)g_xh)[i] = make_uint2(cvth2(v.x, v.y), cvth2(v.z, v.w));
}

// transpose + round: src[e][R][C] fp32 -> g_wtr [e][C][R] single fp16 (R13-verified order)
__global__ void split_w_kernel(const float* __restrict__ src, int R, int C) {
    __shared__ float t[32][33];
    int e = blockIdx.z;
    int c0 = blockIdx.x * 32, r0 = blockIdx.y * 32;
    int tx = threadIdx.x, ty = threadIdx.y;     // 32 x 8
    const float* s = src + (size_t)e * R * C;
#pragma unroll
    for (int i = 0; i < 4; i++)
        t[ty + i * 8][tx] = s[(size_t)(r0 + ty + i * 8) * C + c0 + tx];
    __syncthreads();
    size_t base = (size_t)e * R * C;
    int tfl = ty * 32 + tx;                     // 0..255
    int c = tfl >> 3;                           // 0..31
#pragma unroll
    for (int it = 0; it < 2; it++) {
        int p = (tfl & 7) + it * 8;             // row-pair index 0..15
        float v0 = t[2 * p][c], v1 = t[2 * p + 1][c];
        size_t o = base + (size_t)(c0 + c) * R + r0 + 2 * p;
        *(uint32_t*)((uint16_t*)g_wtr + o) = cvth2(v0, v1);
    }
}

// ---------------- HMMA GEMM (single fp16 x single fp16) ----------------
// Stage (16KB) covers k32: 128 rows x 128B. Row r, chunk c at slot ((c ^ (r&7)) << 4):
//   c0..c3: A k0-31 (16B = 8 fp16 each) | c4..c7: B k0-31
// 2-stage ring = 32KB static smem. 256 threads, 8 warps 4x2, warp tile 32x64.
#define BM 128
#define BN 128
#define STAGE_BYTES 16384

// cp.async 2 chunks (32B) of row r at chunk base c0q, from fp16 row p + byte offset kb
__device__ __forceinline__ void cp2(uint32_t sb, int r, uint32_t c0q, const char* p, size_t kb) {
    uint32_t rb = sb + (uint32_t)r * 128;
    uint32_t rx = (uint32_t)(r & 7);
    cp16(rb + ((c0q ^ rx) << 4), p + kb);
    cp16(rb + (((c0q + 1u) ^ rx) << 4), p + kb + 16);
}

// one k16 block (s = 0 or 1 within the stage); acc[16][4]; 16 MMAs.
__device__ __forceinline__ void compute_k16(uint32_t sb, int s, float acc[16][4]) {
    int tid = threadIdx.x;
    int lane = tid & 31;
    int wid = tid >> 5;
    int wm = (wid & 3) * 32;
    int wn = (wid >> 2) * 64;
    int g = lane >> 3, lr = lane & 7;

    int aRow0 = wm + ((g & 1) << 3) + lr;
    uint32_t ah = (uint32_t)(g >> 1);            // k-half
    int bRow0 = wn + ((g >> 1) << 3) + lr;
    uint32_t bh_ = (uint32_t)(g & 1);

    uint32_t A[2][4];
#pragma unroll
    for (int t = 0; t < 2; t++) {
        uint32_t row = (uint32_t)(aRow0 + 16 * t);
        uint32_t rb = sb + row * 128, rx = row & 7;
        ldsm4(A[t], rb + ((((uint32_t)(2 * s) + ah) ^ rx) << 4));
    }
#pragma unroll
    for (int q = 0; q < 4; q++) {
        uint32_t B[4];
        uint32_t row = (uint32_t)(bRow0 + 16 * q);
        uint32_t rb = sb + row * 128, rx = row & 7;
        ldsm4(B, rb + ((((uint32_t)(4 + 2 * s) + bh_) ^ rx) << 4));
#pragma unroll
        for (int t = 0; t < 2; t++)
#pragma unroll
            for (int jj = 0; jj < 2; jj++)
                mma_fp16(acc[t * 8 + q * 2 + jj], A[t], &B[jj * 2]);
    }
}

// 2-stage mainloop, both operands async. Threads <128 load A row r, >=128 load B row r.
template <int KT>
__device__ __forceinline__ void gemm_mainloop(uint32_t sbase, int r, bool isA,
                                              const char* p, float acc[16][4]) {
    uint32_t cb = isA ? 0u : 4u;
    cp2(sbase, r, cb, p, 0);
    cp2(sbase, r, cb + 2u, p, 32);
    CP_COMMIT();
    CP_WAIT0();
    __syncthreads();
    for (int kt = 0; kt < KT; kt++) {
        uint32_t cur = sbase + (uint32_t)(kt & 1) * STAGE_BYTES;
        uint32_t nxt = sbase + (uint32_t)((kt + 1) & 1) * STAGE_BYTES;
        bool more = (kt + 1 < KT);
        size_t kb = (size_t)(kt + 1) * 64;   // (kt+1)*32 fp16 * 2B
        if (more) cp2(nxt, r, cb, p, kb);            // prefetch first half
        compute_k16(cur, 0, acc);
        if (more) { cp2(nxt, r, cb + 2u, p, kb + 32); CP_COMMIT(); }
        compute_k16(cur, 1, acc);
        CP_WAIT0();
        __syncthreads();
    }
}

// GEMM1: h = gelu(x[tok] @ W1[e] + b1) -> g_hh (fp16)
__global__ __launch_bounds__(256, 2)
void gemm1_kernel(const float* __restrict__ b1) {
    __shared__ __align__(128) char smem[2 * STAGE_BYTES];
    int e = blockIdx.z;
    int cnt = g_cnt[e];
    int row0 = blockIdx.y * BM;
    if (row0 >= cnt) return;
    int col0 = blockIdx.x * BN;
    int off = g_off[e];
    int tid = threadIdx.x;
    uint32_t sbase = smem_u32(smem);

    int r = tid & 127;
    bool isA = tid < 128;
    const char* p;
    if (isA) {
        int rA = min(row0 + r, cnt - 1);
        p = (const char*)(g_xh + (size_t)g_tok[e * T_TOK + rA] * D_DIM);
    } else {
        p = (const char*)(g_wtr + (size_t)e * H_DIM * D_DIM + (size_t)(col0 + r) * D_DIM);
    }

    float acc[16][4];
#pragma unroll
    for (int i = 0; i < 16; i++)
#pragma unroll
        for (int j = 0; j < 4; j++) acc[i][j] = 0.0f;

    gemm_mainloop<D_DIM / 32>(sbase, r, isA, p, acc);

    // epilogue: bias + gelu -> fp16
    int lane = tid & 31, wid = tid >> 5;
    int wm = (wid & 3) * 32, wn = (wid >> 2) * 64;
    int mrow = row0 + wm + (lane >> 2);
    int ncol = col0 + wn + (lane & 3) * 2;
    const float* bg = b1 + (size_t)e * H_DIM;

#pragma unroll
    for (int t = 0; t < 2; t++)
#pragma unroll
        for (int j = 0; j < 8; j++) {
            float* c = acc[t * 8 + j];
            int cc = ncol + j * 8;
            float bias0 = bg[cc], bias1 = bg[cc + 1];
            int r1 = mrow + t * 16, r2 = r1 + 8;
            if (r1 < cnt) {
                size_t o = (size_t)(off + r1) * H_DIM + cc;
                *(uint32_t*)(g_hh + o) = cvth2(gelu_exact(c[0] + bias0), gelu_exact(c[1] + bias1));
            }
            if (r2 < cnt) {
                size_t o = (size_t)(off + r2) * H_DIM + cc;
                *(uint32_t*)(g_hh + o) = cvth2(gelu_exact(c[2] + bias0), gelu_exact(c[3] + bias1));
            }
        }
}

// GEMM2: out[tok] += w * (h @ W2[e] + b2)
__global__ __launch_bounds__(256, 2)
void gemm2_kernel(const float* __restrict__ b2, float* __restrict__ out) {
    __shared__ __align__(128) char smem[2 * STAGE_BYTES];
    int e = blockIdx.z;
    int cnt = g_cnt[e];
    int row0 = blockIdx.y * BM;
    if (row0 >= cnt) return;
    int col0 = blockIdx.x * BN;
    int off = g_off[e];
    int tid = threadIdx.x;
    uint32_t sbase = smem_u32(smem);

    int r = tid & 127;
    bool isA = tid < 128;
    const char* p;
    if (isA) {
        int rA = off + min(row0 + r, cnt - 1);
        p = (const char*)(g_hh + (size_t)rA * H_DIM);
    } else {
        p = (const char*)(g_wtr + (size_t)e * H_DIM * D_DIM + (size_t)(col0 + r) * H_DIM);
    }

    float acc[16][4];
#pragma unroll
    for (int i = 0; i < 16; i++)
#pragma unroll
        for (int j = 0; j < 4; j++) acc[i][j] = 0.0f;

    gemm_mainloop<H_DIM / 32>(sbase, r, isA, p, acc);

    int lane = tid & 31, wid = tid >> 5;
    int wm = (wid & 3) * 32, wn = (wid >> 2) * 64;
    int mrow = row0 + wm + (lane >> 2);
    int ncol = col0 + wn + (lane & 3) * 2;
    const float* bg = b2 + (size_t)e * D_DIM;

#pragma unroll
    for (int t = 0; t < 2; t++) {
        int r1 = mrow + t * 16, r2 = r1 + 8;
        int tok1 = 0, tok2 = 0; float w1 = 0.0f, w2 = 0.0f;
        if (r1 < cnt) { tok1 = g_tok[e * T_TOK + r1]; w1 = g_wt[e * T_TOK + r1]; }
        if (r2 < cnt) { tok2 = g_tok[e * T_TOK + r2]; w2 = g_wt[e * T_TOK + r2]; }
#pragma unroll
        for (int j = 0; j < 8; j++) {
            float* c = acc[t * 8 + j];
            int cc = ncol + j * 8;
            float bias0 = bg[cc], bias1 = bg[cc + 1];
            if (r1 < cnt) {
                float* o = out + (size_t)tok1 * D_DIM + cc;
                atomicAdd(o,     w1 * (c[0] + bias0));
                atomicAdd(o + 1, w1 * (c[1] + bias1));
            }
            if (r2 < cnt) {
                float* o = out + (size_t)tok2 * D_DIM + cc;
                atomicAdd(o,     w2 * (c[2] + bias0));
                atomicAdd(o + 1, w2 * (c[3] + bias1));
            }
        }
    }
}

// ---------------- launch ----------------
extern "C" void kernel_launch(void* const* d_in, const int* in_sizes, int n_in,
                              void* d_out, int out_size) {
    const float* x  = (const float*)d_in[0];
    const float* Wg = (const float*)d_in[1];
    const float* W1 = (const float*)d_in[2];
    const float* b1 = (const float*)d_in[3];
    const float* W2 = (const float*)d_in[4];
    const float* b2 = (const float*)d_in[5];
    float* out = (float*)d_out;

    zero_kernel<<<4096, 256>>>(out, out_size);
    router_kernel<<<T_TOK / 8, 256>>>(x, Wg);
    scan_kernel<<<1, 32>>>();
    split_x_kernel<<<(T_TOK * D_DIM / 4 + 255) / 256, 256>>>(x);

    // W1 [E][D][H] -> W1t [E][H][D] single fp16 (shared buffer)
    split_w_kernel<<<dim3(H_DIM / 32, D_DIM / 32, E_EXP), dim3(32, 8)>>>(W1, D_DIM, H_DIM);
    gemm1_kernel<<<dim3(H_DIM / BN, T_TOK / BM, E_EXP), 256>>>(b1);

    // W2 [E][H][D] -> W2t [E][D][H] single fp16 (same buffer, stream-ordered)
    split_w_kernel<<<dim3(D_DIM / 32, H_DIM / 32, E_EXP), dim3(32, 8)>>>(W2, H_DIM, D_DIM);
    gemm2_kernel<<<dim3(D_DIM / BN, T_TOK / BM, E_EXP), 256>>>(b2, out);
}

// round 16
// speedup vs baseline: 1.9720x; 1.0410x over previous
#include <cuda_runtime.h>
#include <cuda_fp16.h>
#include <math.h>
#include <stdint.h>

// Problem constants (fixed by the dataset)
#define T_TOK 8192
#define D_DIM 1024
#define E_EXP 8
#define H_DIM 4096

// ---------------- device-global scratch ----------------
__device__ int   g_cnt[E_EXP];
__device__ int   g_off[E_EXP];
__device__ int   g_tok[E_EXP * T_TOK];
__device__ float g_wt [E_EXP * T_TOK];
__device__ __align__(256) __half g_xh [(size_t)T_TOK * D_DIM];             // x fp16
// shared transposed-weight buffer (single fp16): W1t during gemm1, W2t during gemm2
__device__ __align__(256) __half g_wtr[(size_t)E_EXP * H_DIM * D_DIM];
__device__ __align__(256) __half g_hh [(size_t)T_TOK * 2 * H_DIM];         // h fp16

// ---------------- helpers ----------------
__device__ __forceinline__ uint32_t smem_u32(const void* p) {
    uint32_t a;
    asm("{ .reg .u64 t; cvta.to.shared.u64 t, %1; cvt.u32.u64 %0, t; }" : "=r"(a) : "l"(p));
    return a;
}
__device__ __forceinline__ void ldsm4(uint32_t* r, uint32_t addr) {
    asm volatile("ldmatrix.sync.aligned.m8n8.x4.shared.b16 {%0,%1,%2,%3}, [%4];"
                 : "=r"(r[0]), "=r"(r[1]), "=r"(r[2]), "=r"(r[3]) : "r"(addr));
}
__device__ __forceinline__ void mma_fp16(float* c, const uint32_t* a, const uint32_t* b) {
    asm volatile("mma.sync.aligned.m16n8k16.row.col.f32.f16.f16.f32 "
                 "{%0,%1,%2,%3}, {%4,%5,%6,%7}, {%8,%9}, {%0,%1,%2,%3};"
                 : "+f"(c[0]), "+f"(c[1]), "+f"(c[2]), "+f"(c[3])
                 : "r"(a[0]), "r"(a[1]), "r"(a[2]), "r"(a[3]), "r"(b[0]), "r"(b[1]));
}
__device__ __forceinline__ void cp16(uint32_t s, const void* g) {
    asm volatile("cp.async.cg.shared.global [%0], [%1], 16;" :: "r"(s), "l"(g) : "memory");
}
#define CP_COMMIT() asm volatile("cp.async.commit_group;" ::: "memory")
#define CP_WAIT2()  asm volatile("cp.async.wait_group 2;" ::: "memory")

__device__ __forceinline__ uint32_t cvth2(float a, float b) {
    __half2 t = __floats2half2_rn(a, b);
    return *(uint32_t*)&t;
}
__device__ __forceinline__ float gelu_exact(float v) {
    return 0.5f * v * (1.0f + erff(v * 0.70710678118654752f));
}

// ---------------- small kernels (R1-proven) ----------------
__global__ void zero_kernel(float* __restrict__ out, int n) {
    int i = blockIdx.x * blockDim.x + threadIdx.x;
    if (i < E_EXP) g_cnt[i] = 0;
    for (int j = i; j < n; j += gridDim.x * blockDim.x) out[j] = 0.0f;
}

__global__ void router_kernel(const float* __restrict__ x, const float* __restrict__ Wg) {
    int warp = (blockIdx.x * blockDim.x + threadIdx.x) >> 5;
    int lane = threadIdx.x & 31;
    if (warp >= T_TOK) return;
    const float* xr = x + (size_t)warp * D_DIM;
    float acc[E_EXP];
#pragma unroll
    for (int e = 0; e < E_EXP; e++) acc[e] = 0.0f;
    for (int k = lane; k < D_DIM; k += 32) {
        float xv = xr[k];
        const float* wr = Wg + (size_t)k * E_EXP;
#pragma unroll
        for (int e = 0; e < E_EXP; e++) acc[e] = fmaf(xv, wr[e], acc[e]);
    }
#pragma unroll
    for (int e = 0; e < E_EXP; e++)
#pragma unroll
        for (int o = 16; o > 0; o >>= 1) acc[e] += __shfl_xor_sync(0xffffffffu, acc[e], o);
    if (lane == 0) {
        float mx = acc[0];
#pragma unroll
        for (int e = 1; e < E_EXP; e++) mx = fmaxf(mx, acc[e]);
        float p[E_EXP], s = 0.0f;
#pragma unroll
        for (int e = 0; e < E_EXP; e++) { p[e] = expf(acc[e] - mx); s += p[e]; }
        float inv = 1.0f / s;
        int i1 = 0; float v1 = p[0];
#pragma unroll
        for (int e = 1; e < E_EXP; e++) if (p[e] > v1) { v1 = p[e]; i1 = e; }
        int i2 = -1; float v2 = -1.0f;
#pragma unroll
        for (int e = 0; e < E_EXP; e++) if (e != i1 && p[e] > v2) { v2 = p[e]; i2 = e; }
        int p1 = atomicAdd(&g_cnt[i1], 1);
        g_tok[i1 * T_TOK + p1] = warp; g_wt[i1 * T_TOK + p1] = v1 * inv;
        int p2 = atomicAdd(&g_cnt[i2], 1);
        g_tok[i2 * T_TOK + p2] = warp; g_wt[i2 * T_TOK + p2] = v2 * inv;
    }
}

__global__ void scan_kernel() {
    if (threadIdx.x == 0) {
        int s = 0;
#pragma unroll
        for (int e = 0; e < E_EXP; e++) { g_off[e] = s; s += g_cnt[e]; }
    }
}

// x: fp32 -> single fp16
__global__ void split_x_kernel(const float* __restrict__ x) {
    int i = blockIdx.x * blockDim.x + threadIdx.x;
    int n4 = (T_TOK * D_DIM) / 4;
    if (i >= n4) return;
    float4 v = ((const float4*)x)[i];
    ((uint2*)g_xh)[i] = make_uint2(cvth2(v.x, v.y), cvth2(v.z, v.w));
}

// transpose + round: src[e][R][C] fp32 -> g_wtr [e][C][R] single fp16 (R13-verified order)
__global__ void split_w_kernel(const float* __restrict__ src, int R, int C) {
    __shared__ float t[32][33];
    int e = blockIdx.z;
    int c0 = blockIdx.x * 32, r0 = blockIdx.y * 32;
    int tx = threadIdx.x, ty = threadIdx.y;     // 32 x 8
    const float* s = src + (size_t)e * R * C;
#pragma unroll
    for (int i = 0; i < 4; i++)
        t[ty + i * 8][tx] = s[(size_t)(r0 + ty + i * 8) * C + c0 + tx];
    __syncthreads();
    size_t base = (size_t)e * R * C;
    int tfl = ty * 32 + tx;                     // 0..255
    int c = tfl >> 3;                           // 0..31
#pragma unroll
    for (int it = 0; it < 2; it++) {
        int p = (tfl & 7) + it * 8;             // row-pair index 0..15
        float v0 = t[2 * p][c], v1 = t[2 * p + 1][c];
        size_t o = base + (size_t)(c0 + c) * R + r0 + 2 * p;
        *(uint32_t*)((uint16_t*)g_wtr + o) = cvth2(v0, v1);
    }
}

// ---------------- HMMA GEMM (single fp16 x single fp16) ----------------
// Stage (16KB) covers k32: 128 rows x 128B. Row r, chunk c at slot ((c ^ (r&7)) << 4):
//   c0..c3: A k0-31 | c4..c7: B k0-31
// 4-stage ring = 64KB static smem (R7-proven per-CTA size), 2 CTAs/SM.
#define BM 128
#define BN 128
#define STAGE_BYTES 16384
#define N_BUF 4

// cp.async 2 chunks (32B) of row r at chunk base c0q, from fp16 row p + byte offset kb
__device__ __forceinline__ void cp2(uint32_t sb, int r, uint32_t c0q, const char* p, size_t kb) {
    uint32_t rb = sb + (uint32_t)r * 128;
    uint32_t rx = (uint32_t)(r & 7);
    cp16(rb + ((c0q ^ rx) << 4), p + kb);
    cp16(rb + (((c0q + 1u) ^ rx) << 4), p + kb + 16);
}

// one k16 block (s = 0 or 1 within the stage); acc[16][4]; 16 MMAs.
__device__ __forceinline__ void compute_k16(uint32_t sb, int s, float acc[16][4]) {
    int tid = threadIdx.x;
    int lane = tid & 31;
    int wid = tid >> 5;
    int wm = (wid & 3) * 32;
    int wn = (wid >> 2) * 64;
    int g = lane >> 3, lr = lane & 7;

    int aRow0 = wm + ((g & 1) << 3) + lr;
    uint32_t ah = (uint32_t)(g >> 1);            // k-half
    int bRow0 = wn + ((g >> 1) << 3) + lr;
    uint32_t bh_ = (uint32_t)(g & 1);

    uint32_t A[2][4];
#pragma unroll
    for (int t = 0; t < 2; t++) {
        uint32_t row = (uint32_t)(aRow0 + 16 * t);
        uint32_t rb = sb + row * 128, rx = row & 7;
        ldsm4(A[t], rb + ((((uint32_t)(2 * s) + ah) ^ rx) << 4));
    }
#pragma unroll
    for (int q = 0; q < 4; q++) {
        uint32_t B[4];
        uint32_t row = (uint32_t)(bRow0 + 16 * q);
        uint32_t rb = sb + row * 128, rx = row & 7;
        ldsm4(B, rb + ((((uint32_t)(4 + 2 * s) + bh_) ^ rx) << 4));
#pragma unroll
        for (int t = 0; t < 2; t++)
#pragma unroll
            for (int jj = 0; jj < 2; jj++)
                mma_fp16(acc[t * 8 + q * 2 + jj], A[t], &B[jj * 2]);
    }
}

// 4-stage mainloop, bounded wait_group 2: each buffer has ~2.5 iterations of slack.
// Threads <128 load A row r, >=128 load B row r. One commit per iteration.
template <int KT>
__device__ __forceinline__ void gemm_mainloop(uint32_t sbase, int r, bool isA,
                                              const char* p, float acc[16][4]) {
    uint32_t cb = isA ? 0u : 4u;
    // prologue: fill buffers 0..2 (3 committed groups)
#pragma unroll
    for (int s = 0; s < 3; s++) {
        if (s < KT) {
            cp2(sbase + (uint32_t)s * STAGE_BYTES, r, cb, p, (size_t)s * 64);
            cp2(sbase + (uint32_t)s * STAGE_BYTES, r, cb + 2u, p, (size_t)s * 64 + 32);
        }
        CP_COMMIT();
    }
    CP_WAIT2();          // buffer 0 ready
    __syncthreads();
    int buf = 0;
    for (int kt = 0; kt < KT; kt++) {
        uint32_t cur = sbase + (uint32_t)buf * STAGE_BYTES;
        int nb = buf + 3; if (nb >= N_BUF) nb -= N_BUF;
        uint32_t nxt = sbase + (uint32_t)nb * STAGE_BYTES;
        bool more = (kt + 3 < KT);
        size_t kb = (size_t)(kt + 3) * 64;
        if (more) cp2(nxt, r, cb, p, kb);
        compute_k16(cur, 0, acc);
        if (more) cp2(nxt, r, cb + 2u, p, kb + 32);
        CP_COMMIT();     // one group per iteration (may be empty in the tail)
        compute_k16(cur, 1, acc);
        CP_WAIT2();      // oldest outstanding group (buffer kt+1) completes
        __syncthreads();
        if (++buf == N_BUF) buf = 0;
    }
}

// GEMM1: h = gelu(x[tok] @ W1[e] + b1) -> g_hh (fp16)
__global__ __launch_bounds__(256, 2)
void gemm1_kernel(const float* __restrict__ b1) {
    __shared__ __align__(128) char smem[N_BUF * STAGE_BYTES];
    int e = blockIdx.z;
    int cnt = g_cnt[e];
    int row0 = blockIdx.y * BM;
    if (row0 >= cnt) return;
    int col0 = blockIdx.x * BN;
    int off = g_off[e];
    int tid = threadIdx.x;
    uint32_t sbase = smem_u32(smem);

    int r = tid & 127;
    bool isA = tid < 128;
    const char* p;
    if (isA) {
        int rA = min(row0 + r, cnt - 1);
        p = (const char*)(g_xh + (size_t)g_tok[e * T_TOK + rA] * D_DIM);
    } else {
        p = (const char*)(g_wtr + (size_t)e * H_DIM * D_DIM + (size_t)(col0 + r) * D_DIM);
    }

    float acc[16][4];
#pragma unroll
    for (int i = 0; i < 16; i++)
#pragma unroll
        for (int j = 0; j < 4; j++) acc[i][j] = 0.0f;

    gemm_mainloop<D_DIM / 32>(sbase, r, isA, p, acc);

    // epilogue: bias + gelu -> fp16
    int lane = tid & 31, wid = tid >> 5;
    int wm = (wid & 3) * 32, wn = (wid >> 2) * 64;
    int mrow = row0 + wm + (lane >> 2);
    int ncol = col0 + wn + (lane & 3) * 2;
    const float* bg = b1 + (size_t)e * H_DIM;

#pragma unroll
    for (int t = 0; t < 2; t++)
#pragma unroll
        for (int j = 0; j < 8; j++) {
            float* c = acc[t * 8 + j];
            int cc = ncol + j * 8;
            float bias0 = bg[cc], bias1 = bg[cc + 1];
            int r1 = mrow + t * 16, r2 = r1 + 8;
            if (r1 < cnt) {
                size_t o = (size_t)(off + r1) * H_DIM + cc;
                *(uint32_t*)(g_hh + o) = cvth2(gelu_exact(c[0] + bias0), gelu_exact(c[1] + bias1));
            }
            if (r2 < cnt) {
                size_t o = (size_t)(off + r2) * H_DIM + cc;
                *(uint32_t*)(g_hh + o) = cvth2(gelu_exact(c[2] + bias0), gelu_exact(c[3] + bias1));
            }
        }
}

// GEMM2: out[tok] += w * (h @ W2[e] + b2)
__global__ __launch_bounds__(256, 2)
void gemm2_kernel(const float* __restrict__ b2, float* __restrict__ out) {
    __shared__ __align__(128) char smem[N_BUF * STAGE_BYTES];
    int e = blockIdx.z;
    int cnt = g_cnt[e];
    int row0 = blockIdx.y * BM;
    if (row0 >= cnt) return;
    int col0 = blockIdx.x * BN;
    int off = g_off[e];
    int tid = threadIdx.x;
    uint32_t sbase = smem_u32(smem);

    int r = tid & 127;
    bool isA = tid < 128;
    const char* p;
    if (isA) {
        int rA = off + min(row0 + r, cnt - 1);
        p = (const char*)(g_hh + (size_t)rA * H_DIM);
    } else {
        p = (const char*)(g_wtr + (size_t)e * H_DIM * D_DIM + (size_t)(col0 + r) * H_DIM);
    }

    float acc[16][4];
#pragma unroll
    for (int i = 0; i < 16; i++)
#pragma unroll
        for (int j = 0; j < 4; j++) acc[i][j] = 0.0f;

    gemm_mainloop<H_DIM / 32>(sbase, r, isA, p, acc);

    int lane = tid & 31, wid = tid >> 5;
    int wm = (wid & 3) * 32, wn = (wid >> 2) * 64;
    int mrow = row0 + wm + (lane >> 2);
    int ncol = col0 + wn + (lane & 3) * 2;
    const float* bg = b2 + (size_t)e * D_DIM;

#pragma unroll
    for (int t = 0; t < 2; t++) {
        int r1 = mrow + t * 16, r2 = r1 + 8;
        int tok1 = 0, tok2 = 0; float w1 = 0.0f, w2 = 0.0f;
        if (r1 < cnt) { tok1 = g_tok[e * T_TOK + r1]; w1 = g_wt[e * T_TOK + r1]; }
        if (r2 < cnt) { tok2 = g_tok[e * T_TOK + r2]; w2 = g_wt[e * T_TOK + r2]; }
#pragma unroll
        for (int j = 0; j < 8; j++) {
            float* c = acc[t * 8 + j];
            int cc = ncol + j * 8;
            float bias0 = bg[cc], bias1 = bg[cc + 1];
            if (r1 < cnt) {
                float* o = out + (size_t)tok1 * D_DIM + cc;
                atomicAdd(o,     w1 * (c[0] + bias0));
                atomicAdd(o + 1, w1 * (c[1] + bias1));
            }
            if (r2 < cnt) {
                float* o = out + (size_t)tok2 * D_DIM + cc;
                atomicAdd(o,     w2 * (c[2] + bias0));
                atomicAdd(o + 1, w2 * (c[3] + bias1));
            }
        }
    }
}

// ---------------- launch ----------------
extern "C" void kernel_launch(void* const* d_in, const int* in_sizes, int n_in,
                              void* d_out, int out_size) {
    const float* x  = (const float*)d_in[0];
    const float* Wg = (const float*)d_in[1];
    const float* W1 = (const float*)d_in[2];
    const float* b1 = (const float*)d_in[3];
    const float* W2 = (const float*)d_in[4];
    const float* b2 = (const float*)d_in[5];
    float* out = (float*)d_out;

    zero_kernel<<<4096, 256>>>(out, out_size);
    router_kernel<<<T_TOK / 8, 256>>>(x, Wg);
    scan_kernel<<<1, 32>>>();
    split_x_kernel<<<(T_TOK * D_DIM / 4 + 255) / 256, 256>>>(x);

    // W1 [E][D][H] -> W1t [E][H][D] single fp16 (shared buffer)
    split_w_kernel<<<dim3(H_DIM / 32, D_DIM / 32, E_EXP), dim3(32, 8)>>>(W1, D_DIM, H_DIM);
    gemm1_kernel<<<dim3(H_DIM / BN, T_TOK / BM, E_EXP), 256>>>(b1);

    // W2 [E][H][D] -> W2t [E][D][H] single fp16 (same buffer, stream-ordered)
    split_w_kernel<<<dim3(D_DIM / 32, H_DIM / 32, E_EXP), dim3(32, 8)>>>(W2, H_DIM, D_DIM);
    gemm2_kernel<<<dim3(D_DIM / BN, T_TOK / BM, E_EXP), 256>>>(b2, out);
}

// round 17
// speedup vs baseline: 1.9913x; 1.0098x over previous
#include <cuda_runtime.h>
#include <cuda_fp16.h>
#include <math.h>
#include <stdint.h>

// Problem constants (fixed by the dataset)
#define T_TOK 8192
#define D_DIM 1024
#define E_EXP 8
#define H_DIM 4096

// ---------------- device-global scratch ----------------
__device__ int   g_cnt[E_EXP];
__device__ int   g_off[E_EXP];
__device__ int   g_tok[E_EXP * T_TOK];
__device__ float g_wt [E_EXP * T_TOK];
__device__ __align__(256) __half g_xh [(size_t)T_TOK * D_DIM];             // x fp16
// shared transposed-weight buffer (single fp16): W1t during gemm1, W2t during gemm2
__device__ __align__(256) __half g_wtr[(size_t)E_EXP * H_DIM * D_DIM];
__device__ __align__(256) __half g_hh [(size_t)T_TOK * 2 * H_DIM];         // h fp16

// ---------------- helpers ----------------
__device__ __forceinline__ uint32_t smem_u32(const void* p) {
    uint32_t a;
    asm("{ .reg .u64 t; cvta.to.shared.u64 t, %1; cvt.u32.u64 %0, t; }" : "=r"(a) : "l"(p));
    return a;
}
__device__ __forceinline__ void ldsm4(uint32_t* r, uint32_t addr) {
    asm volatile("ldmatrix.sync.aligned.m8n8.x4.shared.b16 {%0,%1,%2,%3}, [%4];"
                 : "=r"(r[0]), "=r"(r[1]), "=r"(r[2]), "=r"(r[3]) : "r"(addr));
}
__device__ __forceinline__ void mma_fp16(float* c, const uint32_t* a, const uint32_t* b) {
    asm volatile("mma.sync.aligned.m16n8k16.row.col.f32.f16.f16.f32 "
                 "{%0,%1,%2,%3}, {%4,%5,%6,%7}, {%8,%9}, {%0,%1,%2,%3};"
                 : "+f"(c[0]), "+f"(c[1]), "+f"(c[2]), "+f"(c[3])
                 : "r"(a[0]), "r"(a[1]), "r"(a[2]), "r"(a[3]), "r"(b[0]), "r"(b[1]));
}
__device__ __forceinline__ void cp16(uint32_t s, const void* g) {
    asm volatile("cp.async.cg.shared.global [%0], [%1], 16;" :: "r"(s), "l"(g) : "memory");
}
#define CP_COMMIT() asm volatile("cp.async.commit_group;" ::: "memory")
#define CP_WAIT2()  asm volatile("cp.async.wait_group 2;" ::: "memory")

__device__ __forceinline__ uint32_t cvth2(float a, float b) {
    __half2 t = __floats2half2_rn(a, b);
    return *(uint32_t*)&t;
}
__device__ __forceinline__ float gelu_exact(float v) {
    return 0.5f * v * (1.0f + erff(v * 0.70710678118654752f));
}

// ---------------- small kernels (R1-proven) ----------------
__global__ void zero_kernel(float* __restrict__ out, int n) {
    int i = blockIdx.x * blockDim.x + threadIdx.x;
    if (i < E_EXP) g_cnt[i] = 0;
    for (int j = i; j < n; j += gridDim.x * blockDim.x) out[j] = 0.0f;
}

__global__ void router_kernel(const float* __restrict__ x, const float* __restrict__ Wg) {
    int warp = (blockIdx.x * blockDim.x + threadIdx.x) >> 5;
    int lane = threadIdx.x & 31;
    if (warp >= T_TOK) return;
    const float* xr = x + (size_t)warp * D_DIM;
    float acc[E_EXP];
#pragma unroll
    for (int e = 0; e < E_EXP; e++) acc[e] = 0.0f;
    for (int k = lane; k < D_DIM; k += 32) {
        float xv = xr[k];
        const float* wr = Wg + (size_t)k * E_EXP;
#pragma unroll
        for (int e = 0; e < E_EXP; e++) acc[e] = fmaf(xv, wr[e], acc[e]);
    }
#pragma unroll
    for (int e = 0; e < E_EXP; e++)
#pragma unroll
        for (int o = 16; o > 0; o >>= 1) acc[e] += __shfl_xor_sync(0xffffffffu, acc[e], o);
    if (lane == 0) {
        float mx = acc[0];
#pragma unroll
        for (int e = 1; e < E_EXP; e++) mx = fmaxf(mx, acc[e]);
        float p[E_EXP], s = 0.0f;
#pragma unroll
        for (int e = 0; e < E_EXP; e++) { p[e] = expf(acc[e] - mx); s += p[e]; }
        float inv = 1.0f / s;
        int i1 = 0; float v1 = p[0];
#pragma unroll
        for (int e = 1; e < E_EXP; e++) if (p[e] > v1) { v1 = p[e]; i1 = e; }
        int i2 = -1; float v2 = -1.0f;
#pragma unroll
        for (int e = 0; e < E_EXP; e++) if (e != i1 && p[e] > v2) { v2 = p[e]; i2 = e; }
        int p1 = atomicAdd(&g_cnt[i1], 1);
        g_tok[i1 * T_TOK + p1] = warp; g_wt[i1 * T_TOK + p1] = v1 * inv;
        int p2 = atomicAdd(&g_cnt[i2], 1);
        g_tok[i2 * T_TOK + p2] = warp; g_wt[i2 * T_TOK + p2] = v2 * inv;
    }
}

__global__ void scan_kernel() {
    if (threadIdx.x == 0) {
        int s = 0;
#pragma unroll
        for (int e = 0; e < E_EXP; e++) { g_off[e] = s; s += g_cnt[e]; }
    }
}

// x: fp32 -> single fp16
__global__ void split_x_kernel(const float* __restrict__ x) {
    int i = blockIdx.x * blockDim.x + threadIdx.x;
    int n4 = (T_TOK * D_DIM) / 4;
    if (i >= n4) return;
    float4 v = ((const float4*)x)[i];
    ((uint2*)g_xh)[i] = make_uint2(cvth2(v.x, v.y), cvth2(v.z, v.w));
}

// transpose + round: src[e][R][C] fp32 -> g_wtr [e][C][R] single fp16 (R13-verified order)
__global__ void split_w_kernel(const float* __restrict__ src, int R, int C) {
    __shared__ float t[32][33];
    int e = blockIdx.z;
    int c0 = blockIdx.x * 32, r0 = blockIdx.y * 32;
    int tx = threadIdx.x, ty = threadIdx.y;     // 32 x 8
    const float* s = src + (size_t)e * R * C;
#pragma unroll
    for (int i = 0; i < 4; i++)
        t[ty + i * 8][tx] = s[(size_t)(r0 + ty + i * 8) * C + c0 + tx];
    __syncthreads();
    size_t base = (size_t)e * R * C;
    int tfl = ty * 32 + tx;                     // 0..255
    int c = tfl >> 3;                           // 0..31
#pragma unroll
    for (int it = 0; it < 2; it++) {
        int p = (tfl & 7) + it * 8;             // row-pair index 0..15
        float v0 = t[2 * p][c], v1 = t[2 * p + 1][c];
        size_t o = base + (size_t)(c0 + c) * R + r0 + 2 * p;
        *(uint32_t*)((uint16_t*)g_wtr + o) = cvth2(v0, v1);
    }
}

// ---------------- HMMA GEMM (single fp16 x single fp16) ----------------
// Stage (16KB) covers k32: 128 rows x 128B. Row r, chunk c at slot ((c ^ (r&7)) << 4):
//   c0..c3: A k0-31 | c4..c7: B k0-31
// 4-stage ring = 64KB static smem, 2 CTAs/SM.
#define BM 128
#define BN 128
#define STAGE_BYTES 16384
#define N_BUF 4

// cp.async 2 chunks (32B) of row r at chunk base c0q, from fp16 row p + byte offset kb
__device__ __forceinline__ void cp2(uint32_t sb, int r, uint32_t c0q, const char* p, size_t kb) {
    uint32_t rb = sb + (uint32_t)r * 128;
    uint32_t rx = (uint32_t)(r & 7);
    cp16(rb + ((c0q ^ rx) << 4), p + kb);
    cp16(rb + (((c0q + 1u) ^ rx) << 4), p + kb + 16);
}

// one k16 block (s = 0 or 1 within the stage); acc[16][4]; 16 MMAs.
// ALL 6 ldsm are issued up-front so the 16 MMAs run as a dependency-free burst.
__device__ __forceinline__ void compute_k16(uint32_t sb, int s, float acc[16][4]) {
    int tid = threadIdx.x;
    int lane = tid & 31;
    int wid = tid >> 5;
    int wm = (wid & 3) * 32;
    int wn = (wid >> 2) * 64;
    int g = lane >> 3, lr = lane & 7;

    int aRow0 = wm + ((g & 1) << 3) + lr;
    uint32_t ah = (uint32_t)(g >> 1);            // k-half
    int bRow0 = wn + ((g >> 1) << 3) + lr;
    uint32_t bh_ = (uint32_t)(g & 1);

    uint32_t A[2][4];
    uint32_t B[4][4];
#pragma unroll
    for (int t = 0; t < 2; t++) {
        uint32_t row = (uint32_t)(aRow0 + 16 * t);
        uint32_t rb = sb + row * 128, rx = row & 7;
        ldsm4(A[t], rb + ((((uint32_t)(2 * s) + ah) ^ rx) << 4));
    }
#pragma unroll
    for (int q = 0; q < 4; q++) {
        uint32_t row = (uint32_t)(bRow0 + 16 * q);
        uint32_t rb = sb + row * 128, rx = row & 7;
        ldsm4(B[q], rb + ((((uint32_t)(4 + 2 * s) + bh_) ^ rx) << 4));
    }
#pragma unroll
    for (int q = 0; q < 4; q++)
#pragma unroll
        for (int t = 0; t < 2; t++)
#pragma unroll
            for (int jj = 0; jj < 2; jj++)
                mma_fp16(acc[t * 8 + q * 2 + jj], A[t], &B[q][jj * 2]);
}

// 4-stage mainloop, bounded wait_group 2: each buffer has ~2.5 iterations of slack.
// Threads <128 load A row r, >=128 load B row r. One commit per iteration.
template <int KT>
__device__ __forceinline__ void gemm_mainloop(uint32_t sbase, int r, bool isA,
                                              const char* p, float acc[16][4]) {
    uint32_t cb = isA ? 0u : 4u;
    // prologue: fill buffers 0..2 (3 committed groups)
#pragma unroll
    for (int s = 0; s < 3; s++) {
        if (s < KT) {
            cp2(sbase + (uint32_t)s * STAGE_BYTES, r, cb, p, (size_t)s * 64);
            cp2(sbase + (uint32_t)s * STAGE_BYTES, r, cb + 2u, p, (size_t)s * 64 + 32);
        }
        CP_COMMIT();
    }
    CP_WAIT2();          // buffer 0 ready
    __syncthreads();
    int buf = 0;
    for (int kt = 0; kt < KT; kt++) {
        uint32_t cur = sbase + (uint32_t)buf * STAGE_BYTES;
        int nb = buf + 3; if (nb >= N_BUF) nb -= N_BUF;
        uint32_t nxt = sbase + (uint32_t)nb * STAGE_BYTES;
        bool more = (kt + 3 < KT);
        size_t kb = (size_t)(kt + 3) * 64;
        if (more) cp2(nxt, r, cb, p, kb);
        compute_k16(cur, 0, acc);
        if (more) cp2(nxt, r, cb + 2u, p, kb + 32);
        CP_COMMIT();     // one group per iteration (may be empty in the tail)
        compute_k16(cur, 1, acc);
        CP_WAIT2();      // oldest outstanding group (buffer kt+1) completes
        __syncthreads();
        if (++buf == N_BUF) buf = 0;
    }
}

// GEMM1: h = gelu(x[tok] @ W1[e] + b1) -> g_hh (fp16)
__global__ __launch_bounds__(256, 2)
void gemm1_kernel(const float* __restrict__ b1) {
    __shared__ __align__(128) char smem[N_BUF * STAGE_BYTES];
    int e = blockIdx.z;
    int cnt = g_cnt[e];
    int row0 = blockIdx.y * BM;
    if (row0 >= cnt) return;
    int col0 = blockIdx.x * BN;
    int off = g_off[e];
    int tid = threadIdx.x;
    uint32_t sbase = smem_u32(smem);

    int r = tid & 127;
    bool isA = tid < 128;
    const char* p;
    if (isA) {
        int rA = min(row0 + r, cnt - 1);
        p = (const char*)(g_xh + (size_t)g_tok[e * T_TOK + rA] * D_DIM);
    } else {
        p = (const char*)(g_wtr + (size_t)e * H_DIM * D_DIM + (size_t)(col0 + r) * D_DIM);
    }

    float acc[16][4];
#pragma unroll
    for (int i = 0; i < 16; i++)
#pragma unroll
        for (int j = 0; j < 4; j++) acc[i][j] = 0.0f;

    gemm_mainloop<D_DIM / 32>(sbase, r, isA, p, acc);

    // epilogue: bias + gelu -> fp16
    int lane = tid & 31, wid = tid >> 5;
    int wm = (wid & 3) * 32, wn = (wid >> 2) * 64;
    int mrow = row0 + wm + (lane >> 2);
    int ncol = col0 + wn + (lane & 3) * 2;
    const float* bg = b1 + (size_t)e * H_DIM;

#pragma unroll
    for (int t = 0; t < 2; t++)
#pragma unroll
        for (int j = 0; j < 8; j++) {
            float* c = acc[t * 8 + j];
            int cc = ncol + j * 8;
            float bias0 = bg[cc], bias1 = bg[cc + 1];
            int r1 = mrow + t * 16, r2 = r1 + 8;
            if (r1 < cnt) {
                size_t o = (size_t)(off + r1) * H_DIM + cc;
                *(uint32_t*)(g_hh + o) = cvth2(gelu_exact(c[0] + bias0), gelu_exact(c[1] + bias1));
            }
            if (r2 < cnt) {
                size_t o = (size_t)(off + r2) * H_DIM + cc;
                *(uint32_t*)(g_hh + o) = cvth2(gelu_exact(c[2] + bias0), gelu_exact(c[3] + bias1));
            }
        }
}

// GEMM2: out[tok] += w * (h @ W2[e] + b2)
__global__ __launch_bounds__(256, 2)
void gemm2_kernel(const float* __restrict__ b2, float* __restrict__ out) {
    __shared__ __align__(128) char smem[N_BUF * STAGE_BYTES];
    int e = blockIdx.z;
    int cnt = g_cnt[e];
    int row0 = blockIdx.y * BM;
    if (row0 >= cnt) return;
    int col0 = blockIdx.x * BN;
    int off = g_off[e];
    int tid = threadIdx.x;
    uint32_t sbase = smem_u32(smem);

    int r = tid & 127;
    bool isA = tid < 128;
    const char* p;
    if (isA) {
        int rA = off + min(row0 + r, cnt - 1);
        p = (const char*)(g_hh + (size_t)rA * H_DIM);
    } else {
        p = (const char*)(g_wtr + (size_t)e * H_DIM * D_DIM + (size_t)(col0 + r) * H_DIM);
    }

    float acc[16][4];
#pragma unroll
    for (int i = 0; i < 16; i++)
#pragma unroll
        for (int j = 0; j < 4; j++) acc[i][j] = 0.0f;

    gemm_mainloop<H_DIM / 32>(sbase, r, isA, p, acc);

    int lane = tid & 31, wid = tid >> 5;
    int wm = (wid & 3) * 32, wn = (wid >> 2) * 64;
    int mrow = row0 + wm + (lane >> 2);
    int ncol = col0 + wn + (lane & 3) * 2;
    const float* bg = b2 + (size_t)e * D_DIM;

#pragma unroll
    for (int t = 0; t < 2; t++) {
        int r1 = mrow + t * 16, r2 = r1 + 8;
        int tok1 = 0, tok2 = 0; float w1 = 0.0f, w2 = 0.0f;
        if (r1 < cnt) { tok1 = g_tok[e * T_TOK + r1]; w1 = g_wt[e * T_TOK + r1]; }
        if (r2 < cnt) { tok2 = g_tok[e * T_TOK + r2]; w2 = g_wt[e * T_TOK + r2]; }
#pragma unroll
        for (int j = 0; j < 8; j++) {
            float* c = acc[t * 8 + j];
            int cc = ncol + j * 8;
            float bias0 = bg[cc], bias1 = bg[cc + 1];
            if (r1 < cnt) {
                float* o = out + (size_t)tok1 * D_DIM + cc;
                atomicAdd(o,     w1 * (c[0] + bias0));
                atomicAdd(o + 1, w1 * (c[1] + bias1));
            }
            if (r2 < cnt) {
                float* o = out + (size_t)tok2 * D_DIM + cc;
                atomicAdd(o,     w2 * (c[2] + bias0));
                atomicAdd(o + 1, w2 * (c[3] + bias1));
            }
        }
    }
}

// ---------------- launch ----------------
extern "C" void kernel_launch(void* const* d_in, const int* in_sizes, int n_in,
                              void* d_out, int out_size) {
    const float* x  = (const float*)d_in[0];
    const float* Wg = (const float*)d_in[1];
    const float* W1 = (const float*)d_in[2];
    const float* b1 = (const float*)d_in[3];
    const float* W2 = (const float*)d_in[4];
    const float* b2 = (const float*)d_in[5];
    float* out = (float*)d_out;

    zero_kernel<<<4096, 256>>>(out, out_size);
    router_kernel<<<T_TOK / 8, 256>>>(x, Wg);
    scan_kernel<<<1, 32>>>();
    split_x_kernel<<<(T_TOK * D_DIM / 4 + 255) / 256, 256>>>(x);

    // W1 [E][D][H] -> W1t [E][H][D] single fp16 (shared buffer)
    split_w_kernel<<<dim3(H_DIM / 32, D_DIM / 32, E_EXP), dim3(32, 8)>>>(W1, D_DIM, H_DIM);
    gemm1_kernel<<<dim3(H_DIM / BN, T_TOK / BM, E_EXP), 256>>>(b1);

    // W2 [E][H][D] -> W2t [E][D][H] single fp16 (same buffer, stream-ordered)
    split_w_kernel<<<dim3(D_DIM / 32, H_DIM / 32, E_EXP), dim3(32, 8)>>>(W2, H_DIM, D_DIM);
    gemm2_kernel<<<dim3(D_DIM / BN, T_TOK / BM, E_EXP), 256>>>(b2, out);
}